// round 6
// baseline (speedup 1.0000x reference)
#include <cuda_runtime.h>
#include <cuda_fp16.h>
#include <cstdint>

// EmbeddingBag(mode='sum') + bias, L2-traffic-optimized:
//  1) convert fp32 table -> fp16 scratch (halves gather bytes; rel_err ~2e-4)
//  2) gather with PASS PARTITIONING: 16 passes over index ranges of 384 rows
//     (192KB fp16 slice <= 228KB L1), so concurrent warps hit the same hot
//     slice in L1 instead of streaming the whole 3MB table from L2.
//     Indices live in registers (1 coalesced load), extracted per pass via
//     ballot/ffs/shfl. fp16 tree-of-4 pending pipeline keeps cvt count and
//     numeric error identical to the previous best kernel.

#define HIDDEN        256
#define MAX_ROWS      6144
#define ROW_U4        32      // 256 halves = 512B = 32 uint4 per row
#define ROWS_PER_PASS 384     // 384 rows * 512B = 192KB slice
#define SENTINEL      0x7fffffff

__device__ __half g_table_h[MAX_ROWS * HIDDEN];   // 3 MB scratch

__device__ __forceinline__ unsigned h2_to_u(__half2 h) {
    unsigned u; memcpy(&u, &h, 4); return u;
}
__device__ __forceinline__ __half2 u_to_h2(unsigned u) {
    __half2 h; memcpy(&h, &u, 4); return h;
}

// ---------------- phase 1: fp32 -> fp16 convert ----------------
__global__ __launch_bounds__(256)
void convert_kernel(const float4* __restrict__ table4, int n8)
{
    int t = blockIdx.x * blockDim.x + threadIdx.x;
    if (t >= n8) return;
    float4 a = __ldg(table4 + 2 * t);
    float4 b = __ldg(table4 + 2 * t + 1);
    uint4 v;
    v.x = h2_to_u(__floats2half2_rn(a.x, a.y));
    v.y = h2_to_u(__floats2half2_rn(a.z, a.w));
    v.z = h2_to_u(__floats2half2_rn(b.x, b.y));
    v.w = h2_to_u(__floats2half2_rn(b.z, b.w));
    reinterpret_cast<uint4*>(g_table_h)[t] = v;
}

// ---------------- phase 2: pass-partitioned gather ----------------
__device__ __forceinline__ uint4 hadd2x4(const uint4& a, const uint4& b)
{
    uint4 r;
    r.x = h2_to_u(__hadd2(u_to_h2(a.x), u_to_h2(b.x)));
    r.y = h2_to_u(__hadd2(u_to_h2(a.y), u_to_h2(b.y)));
    r.z = h2_to_u(__hadd2(u_to_h2(a.z), u_to_h2(b.z)));
    r.w = h2_to_u(__hadd2(u_to_h2(a.w), u_to_h2(b.w)));
    return r;
}

__device__ __forceinline__ void cvt_acc(float acc[8], const uint4& v)
{
    float2 f0 = __half22float2(u_to_h2(v.x));
    float2 f1 = __half22float2(u_to_h2(v.y));
    float2 f2 = __half22float2(u_to_h2(v.z));
    float2 f3 = __half22float2(u_to_h2(v.w));
    acc[0] += f0.x; acc[1] += f0.y;
    acc[2] += f1.x; acc[3] += f1.y;
    acc[4] += f2.x; acc[5] += f2.y;
    acc[6] += f3.x; acc[7] += f3.y;
}

// cross-pass fp16 tree-of-4 pipeline: p1 holds 1 row, p2 holds a 2-row sum.
// completes a 4-row balanced tree before each fp32 convert (same numerics
// as the previous kernel's tree4).
#define PUSH_ROW(v)                                              \
    do {                                                         \
        if (!have1) { p1 = (v); have1 = 1; }                     \
        else {                                                   \
            uint4 _t = hadd2x4(p1, (v)); have1 = 0;              \
            if (!have2) { p2 = _t; have2 = 1; }                  \
            else { uint4 _s = hadd2x4(p2, _t); have2 = 0;        \
                   cvt_acc(acc, _s); }                           \
        }                                                        \
    } while (0)

__global__ __launch_bounds__(512)
void embag_pass_kernel(const int* __restrict__ idx,
                       const int* __restrict__ offs,
                       const float* __restrict__ bias,
                       float* __restrict__ out,
                       int batch, int n_total, int rows)
{
    const int warp = (blockIdx.x * blockDim.x + threadIdx.x) >> 5;
    const int lane = threadIdx.x & 31;
    const bool active = (warp < batch);

    int start = 0, end = 0;
    if (active) {
        start = __ldg(offs + warp);
        end   = (warp + 1 < batch) ? __ldg(offs + warp + 1) : n_total;
    }
    const int n = end - start;

    // Bag indices in registers (up to 64); overflow handled in-loop.
    int idxA = SENTINEL, idxB = SENTINEL;
    if (lane < n)      idxA = __ldg(idx + start + lane);
    if (32 + lane < n) idxB = __ldg(idx + start + 32 + lane);

    float acc[8];
    {
        float4 b0 = __ldg(reinterpret_cast<const float4*>(bias) + 2 * lane);
        float4 b1 = __ldg(reinterpret_cast<const float4*>(bias) + 2 * lane + 1);
        acc[0] = b0.x; acc[1] = b0.y; acc[2] = b0.z; acc[3] = b0.w;
        acc[4] = b1.x; acc[5] = b1.y; acc[6] = b1.z; acc[7] = b1.w;
    }

    const uint4* base = reinterpret_cast<const uint4*>(g_table_h) + lane;

    uint4 p1, p2;
    int have1 = 0, have2 = 0;

    for (int lo = 0; lo < rows; lo += ROWS_PER_PASS) {
        const int hi = lo + ROWS_PER_PASS;

        // extract matching indices from idxA
        unsigned mask = __ballot_sync(0xffffffffu, idxA >= lo && idxA < hi);
        while (mask) {
            const int b = __ffs(mask) - 1;
            mask &= mask - 1;
            const int i = __shfl_sync(0xffffffffu, idxA, b);
            const uint4 v = base[(size_t)i * ROW_U4];
            PUSH_ROW(v);
        }
        // extract matching indices from idxB
        mask = __ballot_sync(0xffffffffu, idxB >= lo && idxB < hi);
        while (mask) {
            const int b = __ffs(mask) - 1;
            mask &= mask - 1;
            const int i = __shfl_sync(0xffffffffu, idxB, b);
            const uint4 v = base[(size_t)i * ROW_U4];
            PUSH_ROW(v);
        }
        // rare: bags longer than 64 indices
        if (n > 64) {
            for (int k = 64; k < n; ++k) {
                const int i = __ldg(idx + start + k);
                if (i >= lo && i < hi) {
                    const uint4 v = base[(size_t)i * ROW_U4];
                    PUSH_ROW(v);
                }
            }
        }

        __syncthreads();   // keep this CTA's warps on the same hot slice
    }

    if (have2) cvt_acc(acc, p2);
    if (have1) cvt_acc(acc, p1);

    if (active) {
        float4* o = reinterpret_cast<float4*>(out + (size_t)warp * HIDDEN) + 2 * lane;
        o[0] = make_float4(acc[0], acc[1], acc[2], acc[3]);
        o[1] = make_float4(acc[4], acc[5], acc[6], acc[7]);
    }
}

extern "C" void kernel_launch(void* const* d_in, const int* in_sizes, int n_in,
                              void* d_out, int out_size)
{
    const int*    feature_indices = (const int*)d_in[0];
    const int*    offsets         = (const int*)d_in[1];
    const float4* table4          = (const float4*)d_in[2];
    const float*  bias            = (const float*)d_in[3];
    float*        out             = (float*)d_out;

    const int n_total     = in_sizes[0];
    const int batch       = in_sizes[1];
    const int table_elems = in_sizes[2];
    const int rows        = table_elems / HIDDEN;
    const int n8          = table_elems / 8;

    // Maximize L1D (we use no shared memory).
    static int carveout_set = 0;
    if (!carveout_set) {
        cudaFuncSetAttribute(embag_pass_kernel,
                             cudaFuncAttributePreferredSharedMemoryCarveout, 0);
        carveout_set = 1;
    }

    convert_kernel<<<(n8 + 255) / 256, 256>>>(table4, n8);

    const int warps_per_block = 512 / 32;   // 16 bags per CTA
    const int grid = (batch + warps_per_block - 1) / warps_per_block;
    embag_pass_kernel<<<grid, 512>>>(feature_indices, offsets, bias, out,
                                     batch, n_total, rows);
}

// round 7
// speedup vs baseline: 2.7068x; 2.7068x over previous
#include <cuda_runtime.h>
#include <cuda_fp16.h>
#include <cstdint>

// EmbeddingBag(mode='sum') + bias, two-phase:
//  1) convert fp32 table -> fp16 scratch (__device__ global)
//  2) gather-sum fp16 rows (one warp per bag), fp16 tree-of-4 partial sums,
//     fp32 accumulate. This round: 64-thread CTAs (fine-grained tail) and
//     software-pipelined index prefetch (idx loads one group ahead).

#define HIDDEN   256
#define MAX_ROWS 6144
#define ROW_U4   32   // 256 halves = 512B = 32 uint4 per row

__device__ __half g_table_h[MAX_ROWS * HIDDEN];   // 3 MB scratch

__device__ __forceinline__ unsigned h2_to_u(__half2 h) {
    unsigned u; memcpy(&u, &h, 4); return u;
}
__device__ __forceinline__ __half2 u_to_h2(unsigned u) {
    __half2 h; memcpy(&h, &u, 4); return h;
}

// ---------------- phase 1: fp32 -> fp16 convert ----------------
__global__ __launch_bounds__(128)
void convert_kernel(const float4* __restrict__ table4, int n8)
{
    int t = blockIdx.x * blockDim.x + threadIdx.x;
    if (t >= n8) return;
    float4 a = __ldg(table4 + 2 * t);
    float4 b = __ldg(table4 + 2 * t + 1);
    uint4 v;
    v.x = h2_to_u(__floats2half2_rn(a.x, a.y));
    v.y = h2_to_u(__floats2half2_rn(a.z, a.w));
    v.z = h2_to_u(__floats2half2_rn(b.x, b.y));
    v.w = h2_to_u(__floats2half2_rn(b.z, b.w));
    reinterpret_cast<uint4*>(g_table_h)[t] = v;
}

// ---------------- phase 2: gather-sum ----------------
__device__ __forceinline__ void tree4_acc(float acc[8],
                                          const uint4& v0, const uint4& v1,
                                          const uint4& v2, const uint4& v3)
{
    __half2 s0 = __hadd2(__hadd2(u_to_h2(v0.x), u_to_h2(v1.x)),
                         __hadd2(u_to_h2(v2.x), u_to_h2(v3.x)));
    __half2 s1 = __hadd2(__hadd2(u_to_h2(v0.y), u_to_h2(v1.y)),
                         __hadd2(u_to_h2(v2.y), u_to_h2(v3.y)));
    __half2 s2 = __hadd2(__hadd2(u_to_h2(v0.z), u_to_h2(v1.z)),
                         __hadd2(u_to_h2(v2.z), u_to_h2(v3.z)));
    __half2 s3 = __hadd2(__hadd2(u_to_h2(v0.w), u_to_h2(v1.w)),
                         __hadd2(u_to_h2(v2.w), u_to_h2(v3.w)));
    float2 f0 = __half22float2(s0);
    float2 f1 = __half22float2(s1);
    float2 f2 = __half22float2(s2);
    float2 f3 = __half22float2(s3);
    acc[0] += f0.x; acc[1] += f0.y;
    acc[2] += f1.x; acc[3] += f1.y;
    acc[4] += f2.x; acc[5] += f2.y;
    acc[6] += f3.x; acc[7] += f3.y;
}

__device__ __forceinline__ void one_acc(float acc[8], const uint4& v)
{
    float2 f0 = __half22float2(u_to_h2(v.x));
    float2 f1 = __half22float2(u_to_h2(v.y));
    float2 f2 = __half22float2(u_to_h2(v.z));
    float2 f3 = __half22float2(u_to_h2(v.w));
    acc[0] += f0.x; acc[1] += f0.y;
    acc[2] += f1.x; acc[3] += f1.y;
    acc[4] += f2.x; acc[5] += f2.y;
    acc[6] += f3.x; acc[7] += f3.y;
}

// 64-thread CTAs: 2 warps = 2 bags. Fine CTA granularity minimizes the
// wave-quantization tail (equal-duration bags).
__global__ __launch_bounds__(64)
void embag_h_kernel(const int* __restrict__ idx,
                    const int* __restrict__ offs,
                    const float* __restrict__ bias,
                    float* __restrict__ out,
                    int batch, int n_total)
{
    const int warp = blockIdx.x * 2 + (threadIdx.x >> 5);
    const int lane = threadIdx.x & 31;
    if (warp >= batch) return;

    const int start = __ldg(offs + warp);
    const int end   = (warp + 1 < batch) ? __ldg(offs + warp + 1) : n_total;

    float acc[8];
    {
        float4 b0 = __ldg(reinterpret_cast<const float4*>(bias) + 2 * lane);
        float4 b1 = __ldg(reinterpret_cast<const float4*>(bias) + 2 * lane + 1);
        acc[0] = b0.x; acc[1] = b0.y; acc[2] = b0.z; acc[3] = b0.w;
        acc[4] = b1.x; acc[5] = b1.y; acc[6] = b1.z; acc[7] = b1.w;
    }

    const uint4* base = reinterpret_cast<const uint4*>(g_table_h) + lane;

    int j = start;
    if (j + 4 <= end) {
        // software pipeline: indices for the current group loaded one
        // iteration ahead of their row loads.
        int i0 = __ldg(idx + j + 0);
        int i1 = __ldg(idx + j + 1);
        int i2 = __ldg(idx + j + 2);
        int i3 = __ldg(idx + j + 3);
        for (; j + 8 <= end; j += 4) {
            const int n0 = __ldg(idx + j + 4);
            const int n1 = __ldg(idx + j + 5);
            const int n2 = __ldg(idx + j + 6);
            const int n3 = __ldg(idx + j + 7);
            const uint4 v0 = base[(size_t)i0 * ROW_U4];
            const uint4 v1 = base[(size_t)i1 * ROW_U4];
            const uint4 v2 = base[(size_t)i2 * ROW_U4];
            const uint4 v3 = base[(size_t)i3 * ROW_U4];
            tree4_acc(acc, v0, v1, v2, v3);
            i0 = n0; i1 = n1; i2 = n2; i3 = n3;
        }
        // drain the last full group
        {
            const uint4 v0 = base[(size_t)i0 * ROW_U4];
            const uint4 v1 = base[(size_t)i1 * ROW_U4];
            const uint4 v2 = base[(size_t)i2 * ROW_U4];
            const uint4 v3 = base[(size_t)i3 * ROW_U4];
            tree4_acc(acc, v0, v1, v2, v3);
            j += 4;
        }
    }
    // singles tail
    for (; j < end; ++j) {
        const int i = __ldg(idx + j);
        one_acc(acc, base[(size_t)i * ROW_U4]);
    }

    float4* o = reinterpret_cast<float4*>(out + (size_t)warp * HIDDEN) + 2 * lane;
    o[0] = make_float4(acc[0], acc[1], acc[2], acc[3]);
    o[1] = make_float4(acc[4], acc[5], acc[6], acc[7]);
}

extern "C" void kernel_launch(void* const* d_in, const int* in_sizes, int n_in,
                              void* d_out, int out_size)
{
    const int*    feature_indices = (const int*)d_in[0];
    const int*    offsets         = (const int*)d_in[1];
    const float4* table4          = (const float4*)d_in[2];
    const float*  bias            = (const float*)d_in[3];
    float*        out             = (float*)d_out;

    const int n_total     = in_sizes[0];
    const int batch       = in_sizes[1];
    const int table_elems = in_sizes[2];
    const int n8          = table_elems / 8;

    convert_kernel<<<(n8 + 127) / 128, 128>>>(table4, n8);

    const int grid = (batch + 1) / 2;   // 2 bags (warps) per 64-thread CTA
    embag_h_kernel<<<grid, 64>>>(feature_indices, offsets, bias, out,
                                 batch, n_total);
}

// round 8
// speedup vs baseline: 2.9176x; 1.0779x over previous
#include <cuda_runtime.h>
#include <cuda_fp16.h>
#include <cstdint>

// EmbeddingBag(mode='sum') + bias, two-phase:
//  1) convert fp32 table -> fp16 scratch
//  2) gather-sum: one warp per bag; each row read as 2x LDG.64 (lane owns
//     uint2 chunks {lane, lane+32}) to avoid within-LDG wavefront replays;
//     balanced fp16 tree-of-8 (two tree-of-4 groups combined in fp16)
//     before each fp32 convert+accumulate.

#define HIDDEN   256
#define MAX_ROWS 6144
#define ROW_U2   64   // 256 halves = 512B = 64 uint2 chunks per row

__device__ __half g_table_h[MAX_ROWS * HIDDEN];   // 3 MB scratch

__device__ __forceinline__ unsigned h2_to_u(__half2 h) {
    unsigned u; memcpy(&u, &h, 4); return u;
}
__device__ __forceinline__ __half2 u_to_h2(unsigned u) {
    __half2 h; memcpy(&h, &u, 4); return h;
}

// ---------------- phase 1: fp32 -> fp16 convert ----------------
__global__ __launch_bounds__(256)
void convert_kernel(const float4* __restrict__ table4, int n8)
{
    int t = blockIdx.x * blockDim.x + threadIdx.x;
    if (t >= n8) return;
    float4 a = __ldg(table4 + 2 * t);
    float4 b = __ldg(table4 + 2 * t + 1);
    uint4 v;
    v.x = h2_to_u(__floats2half2_rn(a.x, a.y));
    v.y = h2_to_u(__floats2half2_rn(a.z, a.w));
    v.z = h2_to_u(__floats2half2_rn(b.x, b.y));
    v.w = h2_to_u(__floats2half2_rn(b.z, b.w));
    reinterpret_cast<uint4*>(g_table_h)[t] = v;
}

// ---------------- phase 2: gather-sum ----------------
__device__ __forceinline__ uint2 hadd_u2(const uint2& a, const uint2& b)
{
    uint2 r;
    r.x = h2_to_u(__hadd2(u_to_h2(a.x), u_to_h2(b.x)));
    r.y = h2_to_u(__hadd2(u_to_h2(a.y), u_to_h2(b.y)));
    return r;
}

// convert one uint2 (2 half2 = 4 halves) into 4 fp32 adds
__device__ __forceinline__ void cvt_acc4(float* acc, const uint2& v)
{
    float2 f0 = __half22float2(u_to_h2(v.x));
    float2 f1 = __half22float2(u_to_h2(v.y));
    acc[0] += f0.x; acc[1] += f0.y;
    acc[2] += f1.x; acc[3] += f1.y;
}

__global__ __launch_bounds__(64)
void embag_h_kernel(const int* __restrict__ idx,
                    const int* __restrict__ offs,
                    const float* __restrict__ bias,
                    float* __restrict__ out,
                    int batch, int n_total)
{
    const int warp = blockIdx.x * 2 + (threadIdx.x >> 5);
    const int lane = threadIdx.x & 31;
    if (warp >= batch) return;

    const int start = __ldg(offs + warp);
    const int end   = (warp + 1 < batch) ? __ldg(offs + warp + 1) : n_total;

    float acc[8];
    {
        float4 b0 = __ldg(reinterpret_cast<const float4*>(bias) + lane);
        float4 b1 = __ldg(reinterpret_cast<const float4*>(bias) + 32 + lane);
        acc[0] = b0.x; acc[1] = b0.y; acc[2] = b0.z; acc[3] = b0.w;
        acc[4] = b1.x; acc[5] = b1.y; acc[6] = b1.z; acc[7] = b1.w;
    }

    const uint2* tbl = reinterpret_cast<const uint2*>(g_table_h);

    int j = start;
    if (j + 8 <= end) {
        int i0 = __ldg(idx + j + 0), i1 = __ldg(idx + j + 1);
        int i2 = __ldg(idx + j + 2), i3 = __ldg(idx + j + 3);
        int i4 = __ldg(idx + j + 4), i5 = __ldg(idx + j + 5);
        int i6 = __ldg(idx + j + 6), i7 = __ldg(idx + j + 7);
        while (true) {
            const bool more = (j + 16 <= end);
            int n0, n1, n2, n3, n4, n5, n6, n7;
            if (more) {
                n0 = __ldg(idx + j +  8); n1 = __ldg(idx + j +  9);
                n2 = __ldg(idx + j + 10); n3 = __ldg(idx + j + 11);
                n4 = __ldg(idx + j + 12); n5 = __ldg(idx + j + 13);
                n6 = __ldg(idx + j + 14); n7 = __ldg(idx + j + 15);
            }
            // ---- 8 rows, 2x LDG.64 each ----
            const uint2* r0 = tbl + (size_t)i0 * ROW_U2 + lane;
            const uint2* r1 = tbl + (size_t)i1 * ROW_U2 + lane;
            const uint2* r2 = tbl + (size_t)i2 * ROW_U2 + lane;
            const uint2* r3 = tbl + (size_t)i3 * ROW_U2 + lane;
            const uint2* r4 = tbl + (size_t)i4 * ROW_U2 + lane;
            const uint2* r5 = tbl + (size_t)i5 * ROW_U2 + lane;
            const uint2* r6 = tbl + (size_t)i6 * ROW_U2 + lane;
            const uint2* r7 = tbl + (size_t)i7 * ROW_U2 + lane;
            uint2 a0 = r0[0], b0v = r0[32];
            uint2 a1 = r1[0], b1v = r1[32];
            uint2 a2 = r2[0], b2v = r2[32];
            uint2 a3 = r3[0], b3v = r3[32];
            uint2 a4 = r4[0], b4v = r4[32];
            uint2 a5 = r5[0], b5v = r5[32];
            uint2 a6 = r6[0], b6v = r6[32];
            uint2 a7 = r7[0], b7v = r7[32];
            // balanced tree-of-8 in fp16, one cvt per 8 rows
            uint2 sA = hadd_u2(hadd_u2(hadd_u2(a0, a1), hadd_u2(a2, a3)),
                               hadd_u2(hadd_u2(a4, a5), hadd_u2(a6, a7)));
            uint2 sB = hadd_u2(hadd_u2(hadd_u2(b0v, b1v), hadd_u2(b2v, b3v)),
                               hadd_u2(hadd_u2(b4v, b5v), hadd_u2(b6v, b7v)));
            cvt_acc4(acc,     sA);
            cvt_acc4(acc + 4, sB);

            j += 8;
            if (!more) break;
            i0 = n0; i1 = n1; i2 = n2; i3 = n3;
            i4 = n4; i5 = n5; i6 = n6; i7 = n7;
        }
    }
    // tail: group of 4 (balanced tree-of-4)
    if (j + 4 <= end) {
        const int i0 = __ldg(idx + j + 0), i1 = __ldg(idx + j + 1);
        const int i2 = __ldg(idx + j + 2), i3 = __ldg(idx + j + 3);
        const uint2* r0 = tbl + (size_t)i0 * ROW_U2 + lane;
        const uint2* r1 = tbl + (size_t)i1 * ROW_U2 + lane;
        const uint2* r2 = tbl + (size_t)i2 * ROW_U2 + lane;
        const uint2* r3 = tbl + (size_t)i3 * ROW_U2 + lane;
        uint2 sA = hadd_u2(hadd_u2(r0[0], r1[0]), hadd_u2(r2[0], r3[0]));
        uint2 sB = hadd_u2(hadd_u2(r0[32], r1[32]), hadd_u2(r2[32], r3[32]));
        cvt_acc4(acc,     sA);
        cvt_acc4(acc + 4, sB);
        j += 4;
    }
    // singles
    for (; j < end; ++j) {
        const int i = __ldg(idx + j);
        const uint2* r = tbl + (size_t)i * ROW_U2 + lane;
        cvt_acc4(acc,     r[0]);
        cvt_acc4(acc + 4, r[32]);
    }

    float4* o = reinterpret_cast<float4*>(out + (size_t)warp * HIDDEN);
    o[lane]      = make_float4(acc[0], acc[1], acc[2], acc[3]);
    o[32 + lane] = make_float4(acc[4], acc[5], acc[6], acc[7]);
}

extern "C" void kernel_launch(void* const* d_in, const int* in_sizes, int n_in,
                              void* d_out, int out_size)
{
    const int*    feature_indices = (const int*)d_in[0];
    const int*    offsets         = (const int*)d_in[1];
    const float4* table4          = (const float4*)d_in[2];
    const float*  bias            = (const float*)d_in[3];
    float*        out             = (float*)d_out;

    const int n_total     = in_sizes[0];
    const int batch       = in_sizes[1];
    const int table_elems = in_sizes[2];
    const int n8          = table_elems / 8;

    convert_kernel<<<(n8 + 255) / 256, 256>>>(table4, n8);

    const int grid = (batch + 1) / 2;   // 2 bags (warps) per 64-thread CTA
    embag_h_kernel<<<grid, 64>>>(feature_indices, offsets, bias, out,
                                 batch, n_total);
}